// round 14
// baseline (speedup 1.0000x reference)
#include <cuda_runtime.h>
#include <cstdint>

// ============================================================
// BinaryDense: out = sign(x) @ sign(W) + bias ; M=8192,K=2048,N=2048
// Hybrid pipes: warps 0-7 XNOR+POPC (K[0,1344), alu pipe),
//               warps 8-15 mma.sync s8 (K[1344,2048), IMMA pipe).
// R13: KP 1408->1344 (rate-balanced: popc 7.07 K/us, mma 3.61),
//      bits/bytes converts split for coalesced stores.
// ============================================================

#define DIM_M 8192
#define DIM_K 2048
#define DIM_N 2048
#define KW    64                  // bit-words per row, full K

static constexpr int BM = 128;
static constexpr int BN = 64;
static constexpr int KP   = 1344;           // popc K range
static constexpr int KPW  = KP / 32;        // 42 words
static constexpr int KQ   = 10;             // full uint4 groups (40 words) + 1 uint2 tail
static constexpr int KMMA = DIM_K - KP;     // 704
static constexpr int NKT  = KMMA / 64;      // 11 chunks of 64B
static constexpr int KMW4 = KMMA / 4;       // 176 packed-byte words per row
static constexpr int RST  = 44;             // popc row stride (words) = 11 16B-units (odd)

// smem (bytes)
static constexpr int OFF_AP   = 0;                          // 128*44*4 = 22528
static constexpr int OFF_BP   = 128 * RST * 4;              // +64*44*4 = 11264
static constexpr int OFF_MMA  = OFF_BP + 64 * RST * 4;      // 33792
static constexpr int STG_B    = 128 * 64 + 64 * 64;         // 12288 (A=8K,B=4K)
static constexpr int NSTAGE   = 3;
static constexpr int OFF_ACC  = OFF_MMA;                    // epilogue overlay (128*66*4=33792)
static constexpr int SMEM_TOTAL = OFF_MMA + NSTAGE * STG_B; // 70656

// scratch (no allocations allowed)
__device__ uint32_t g_Xp[(size_t)DIM_M * KW];        // bit-packed x, 2MB
__device__ uint32_t g_Wp[(size_t)DIM_N * KW];        // bit-packed W^T, 0.5MB
__device__ int8_t   g_Xb2[(size_t)DIM_M * KMMA];     // byte x, K tail, 5.8MB
__device__ int8_t   g_Wt2[(size_t)DIM_N * KMMA];     // byte W^T, K tail, 1.4MB

// ---------------- helpers ----------------

__device__ __forceinline__ uint32_t smem_u32(const void* p) {
    uint32_t a;
    asm("{ .reg .u64 t; cvta.to.shared.u64 t, %1; cvt.u32.u64 %0, t; }" : "=r"(a) : "l"(p));
    return a;
}
__device__ __forceinline__ constexpr int swz(int r) {   // R4-verified 16B-chunk permute
    return (r & 3) ^ ((r >> 2) & 1);
}
__device__ __forceinline__ void cp_async16(uint32_t dst, const void* src) {
    asm volatile("cp.async.cg.shared.global [%0], [%1], 16;" :: "r"(dst), "l"(src));
}
__device__ __forceinline__ void cp_async8(uint32_t dst, const void* src) {
    asm volatile("cp.async.ca.shared.global [%0], [%1], 8;" :: "r"(dst), "l"(src));
}
#define CP_COMMIT() asm volatile("cp.async.commit_group;" ::: "memory")
#define CP_WAIT(n)  asm volatile("cp.async.wait_group %0;" :: "n"(n) : "memory")
#define NB(id, cnt) asm volatile("bar.sync %0, %1;" :: "r"(id), "r"(cnt) : "memory")

#define LDSM_X4(r0, r1, r2, r3, addr) \
    asm volatile("ldmatrix.sync.aligned.m8n8.x4.shared.b16 {%0,%1,%2,%3}, [%4];" \
                 : "=r"(r0), "=r"(r1), "=r"(r2), "=r"(r3) : "r"(addr))

__device__ __forceinline__ void mma_s8(int* d, const uint32_t* a, const uint32_t* b) {
    asm volatile(
        "mma.sync.aligned.m16n8k32.row.col.s32.s8.s8.s32 "
        "{%0,%1,%2,%3}, {%4,%5,%6,%7}, {%8,%9}, {%0,%1,%2,%3};"
        : "+r"(d[0]), "+r"(d[1]), "+r"(d[2]), "+r"(d[3])
        : "r"(a[0]), "r"(a[1]), "r"(a[2]), "r"(a[3]), "r"(b[0]), "r"(b[1]));
}

// ---------------- profiling-alignment dummy ----------------
__global__ void dummy_kernel() {}

// ---------------- conversion kernels ----------------

// x -> bit-packed signs (full K). Block covers 8192 consecutive floats.
__global__ void convert_x_kernel(const float* __restrict__ x) {
    const int tid = threadIdx.x;                 // 256 thr
    const int lane = tid & 31, warp = tid >> 5;
    const size_t base = (size_t)blockIdx.x * 8192;
#pragma unroll
    for (int i = 0; i < 32; ++i) {
        float v = x[base + (size_t)i * 256 + tid];
        uint32_t word = __ballot_sync(0xFFFFFFFFu, v < 0.0f);
        if (lane == 0) g_Xp[(base >> 5) + i * 8 + warp] = word;
    }
}

// x K-tail -> packed sign bytes (coalesced uint32 stores)
__global__ void convert_xb_kernel(const float* __restrict__ x) {
    const int idx = blockIdx.x * 256 + threadIdx.x;      // one uint32 (4 bytes)
    const int row = idx / KMW4;
    const int c   = idx - row * KMW4;
    const float4 v = *reinterpret_cast<const float4*>(x + (size_t)row * DIM_K + KP + c * 4);
    uint32_t p = (v.x < 0.0f ? 0xFFu : 0x01u)
               | ((v.y < 0.0f ? 0xFFu : 0x01u) << 8)
               | ((v.z < 0.0f ? 0xFFu : 0x01u) << 16)
               | ((v.w < 0.0f ? 0xFFu : 0x01u) << 24);
    reinterpret_cast<uint32_t*>(g_Xb2)[(size_t)row * KMW4 + c] = p;
}

// W[k][n] -> Wp bits [n][kw] + Wt2 bytes [n][k-KP]
__global__ void convert_w_kernel(const float* __restrict__ W) {
    __shared__ float t[32][33];
    const int n0 = blockIdx.x * 32, k0 = blockIdx.y * 32;
    const int tx = threadIdx.x, ty = threadIdx.y;   // (32, 8)
#pragma unroll
    for (int j = 0; j < 32; j += 8)
        t[ty + j][tx] = W[(size_t)(k0 + ty + j) * DIM_N + n0 + tx];
    __syncthreads();
    const int lane = tx, w = ty;
#pragma unroll
    for (int j = 0; j < 4; ++j) {
        int nl = w * 4 + j;
        bool neg = t[lane][nl] < 0.0f;
        uint32_t word = __ballot_sync(0xFFFFFFFFu, neg);
        if (lane == 0) g_Wp[(size_t)(n0 + nl) * KW + (k0 >> 5)] = word;
        if (k0 >= KP)
            g_Wt2[(size_t)(n0 + nl) * KMMA + (k0 - KP) + lane] = neg ? (int8_t)-1 : (int8_t)1;
    }
}

// ---------------- hybrid GEMM ----------------

__global__ void __launch_bounds__(512, 1)
gemm_kernel(const float* __restrict__ bias, float* __restrict__ out) {
    extern __shared__ char smem[];
    const uint32_t sbase = smem_u32(smem);
    const int tid = threadIdx.x;
    const int m0 = blockIdx.y * BM;
    const int n0 = blockIdx.x * BN;

    if (tid < 256) {
        // ================= popc half: K in [0, KP) =================
        const int m_t = tid >> 4;      // 0..15
        const int n_t = tid & 15;      // 0..15

        // load bit tiles: per row, 10 x uint4 + 1 x uint2  (11 transfers)
        for (int t = tid; t < (BM + BN) * 11; t += 256) {
            int r = t / 11, c = t - r * 11;
            uint32_t dst; const uint32_t* src;
            if (r < BM) {
                dst = sbase + OFF_AP + (r * RST) * 4;
                src = g_Xp + (size_t)(m0 + r) * KW;
            } else {
                int rr = r - BM;
                dst = sbase + OFF_BP + (rr * RST) * 4;
                src = g_Wp + (size_t)(n0 + rr) * KW;
            }
            if (c < 10) cp_async16(dst + c * 16, src + c * 4);
            else        cp_async8(dst + 160, src + 40);
        }
        CP_COMMIT(); CP_WAIT(0);
        NB(1, 256);

        const uint32_t* As = reinterpret_cast<const uint32_t*>(smem + OFF_AP);
        const uint32_t* Bs = reinterpret_cast<const uint32_t*>(smem + OFF_BP);

        int acc[8][4];
#pragma unroll
        for (int mi = 0; mi < 8; ++mi)
#pragma unroll
            for (int ni = 0; ni < 4; ++ni) acc[mi][ni] = 0;

#pragma unroll 1
        for (int kq = 0; kq < KQ; ++kq) {
            uint4 b4[4];
#pragma unroll
            for (int ni = 0; ni < 4; ++ni)
                b4[ni] = *reinterpret_cast<const uint4*>(Bs + (n_t + ni * 16) * RST + kq * 4);
#pragma unroll
            for (int mi = 0; mi < 8; ++mi) {
                const uint4 a = *reinterpret_cast<const uint4*>(As + (m_t + mi * 16) * RST + kq * 4);
#pragma unroll
                for (int ni = 0; ni < 4; ++ni) {
                    acc[mi][ni] += __popc(a.x ^ b4[ni].x) + __popc(a.y ^ b4[ni].y)
                                 + __popc(a.z ^ b4[ni].z) + __popc(a.w ^ b4[ni].w);
                }
            }
        }
        // tail group: words 40,41
        {
            uint2 b2[4];
#pragma unroll
            for (int ni = 0; ni < 4; ++ni)
                b2[ni] = *reinterpret_cast<const uint2*>(Bs + (n_t + ni * 16) * RST + 40);
#pragma unroll
            for (int mi = 0; mi < 8; ++mi) {
                const uint2 a = *reinterpret_cast<const uint2*>(As + (m_t + mi * 16) * RST + 40);
#pragma unroll
                for (int ni = 0; ni < 4; ++ni)
                    acc[mi][ni] += __popc(a.x ^ b2[ni].x) + __popc(a.y ^ b2[ni].y);
            }
        }

        NB(0, 512);   // join: mma partials now in smem

        const int* accS = reinterpret_cast<const int*>(smem + OFF_ACC);
        float bn[4];
#pragma unroll
        for (int ni = 0; ni < 4; ++ni) bn[ni] = __ldg(bias + n0 + n_t + ni * 16);
#pragma unroll
        for (int mi = 0; mi < 8; ++mi) {
            const int m = m_t + mi * 16;
            const size_t row = (size_t)(m0 + m) * DIM_N + n0;
#pragma unroll
            for (int ni = 0; ni < 4; ++ni) {
                const int n = n_t + ni * 16;
                out[row + n] = (float)(KP - 2 * acc[mi][ni] + accS[m * 66 + n]) + bn[ni];
            }
        }
    } else {
        // ================= mma half: K in [KP, 2048) =================
        const int tid2 = tid - 256;
        const int w = tid2 >> 5, l = tid2 & 31;      // w 0..7
        const int warp_m = (w >> 2) * 64;            // 2x4 warp grid: 64x16 tiles
        const int warp_n = (w & 3) * 16;

        // ldmatrix lane offsets within a stage (R4-verified; k-step1 = ^32)
        uint32_t aoff[4];
#pragma unroll
        for (int mi = 0; mi < 4; ++mi) {
            int r  = warp_m + mi * 16 + (l & 15);
            int c4 = l >> 4;
            aoff[mi] = (uint32_t)(r * 64 + ((c4 ^ swz(r)) << 4));
        }
        uint32_t boff;
        {
            int nt = (l >> 4) & 1;
            int r  = warp_n + nt * 8 + (l & 7);
            int c4 = (l >> 3) & 1;
            boff = (uint32_t)(128 * 64 + r * 64 + ((c4 ^ swz(r)) << 4));
        }

        const char* Xsrc = reinterpret_cast<const char*>(g_Xb2) + (size_t)m0 * KMMA;
        const char* Wsrc = reinterpret_cast<const char*>(g_Wt2) + (size_t)n0 * KMMA;

        auto load_stage = [&](int kt, int st) {
            const uint32_t base = sbase + OFF_MMA + st * STG_B;
            const int kb = kt * 64;
#pragma unroll
            for (int i = 0; i < 3; ++i) {
                int t = tid2 + i * 256;          // 0..767
                if (t < 512) {
                    int r = t >> 2, c = t & 3;
                    cp_async16(base + r * 64 + ((c ^ swz(r)) << 4),
                               Xsrc + (size_t)r * KMMA + kb + c * 16);
                } else {
                    int u = t - 512;
                    int r = u >> 2, c = u & 3;
                    cp_async16(base + 128 * 64 + r * 64 + ((c ^ swz(r)) << 4),
                               Wsrc + (size_t)r * KMMA + kb + c * 16);
                }
            }
        };

        load_stage(0, 0); CP_COMMIT();
        load_stage(1, 1); CP_COMMIT();

        int acc[4][2][4];
#pragma unroll
        for (int mi = 0; mi < 4; ++mi)
#pragma unroll
            for (int ni = 0; ni < 2; ++ni)
#pragma unroll
                for (int c = 0; c < 4; ++c) acc[mi][ni][c] = 0;

        for (int kt = 0; kt < NKT; ++kt) {
            CP_WAIT(1);
            NB(2, 256);
            if (kt + 2 < NKT) load_stage(kt + 2, (kt + 2) % NSTAGE);
            CP_COMMIT();

            const uint32_t stb = sbase + OFF_MMA + (kt % NSTAGE) * STG_B;
#pragma unroll
            for (int s2 = 0; s2 < 2; ++s2) {
                const uint32_t kxor = s2 * 32;
                uint32_t a[4][4], b[2][2];
#pragma unroll
                for (int mi = 0; mi < 4; ++mi)
                    LDSM_X4(a[mi][0], a[mi][1], a[mi][2], a[mi][3], stb + (aoff[mi] ^ kxor));
                {
                    uint32_t r0, r1, r2, r3;
                    LDSM_X4(r0, r1, r2, r3, stb + (boff ^ kxor));
                    b[0][0] = r0; b[0][1] = r1; b[1][0] = r2; b[1][1] = r3;
                }
#pragma unroll
                for (int mi = 0; mi < 4; ++mi)
#pragma unroll
                    for (int ni = 0; ni < 2; ++ni)
                        mma_s8(acc[mi][ni], a[mi], b[ni]);
            }
        }

        NB(2, 256);   // all mma warps done reading stages
        int* accS = reinterpret_cast<int*>(smem + OFF_ACC);
        const int g = l >> 2, tg = l & 3;
#pragma unroll
        for (int mi = 0; mi < 4; ++mi)
#pragma unroll
            for (int ni = 0; ni < 2; ++ni) {
                const int r = warp_m + mi * 16 + g;
                const int c = warp_n + ni * 8 + 2 * tg;
                accS[r * 66 + c]           = acc[mi][ni][0];
                accS[r * 66 + c + 1]       = acc[mi][ni][1];
                accS[(r + 8) * 66 + c]     = acc[mi][ni][2];
                accS[(r + 8) * 66 + c + 1] = acc[mi][ni][3];
            }

        NB(0, 512);   // join with popc half (which does the combine+store)
    }
}

// ---------------- launch ----------------

extern "C" void kernel_launch(void* const* d_in, const int* in_sizes, int n_in,
                              void* d_out, int out_size) {
    const float* x    = (const float*)d_in[0];   // [8192, 2048]
    const float* W    = (const float*)d_in[1];   // [2048, 2048]
    const float* bias = (const float*)d_in[2];   // [2048]
    float* out = (float*)d_out;                  // [8192, 2048]

    cudaFuncSetAttribute(gemm_kernel, cudaFuncAttributeMaxDynamicSharedMemorySize, SMEM_TOTAL);

    dummy_kernel<<<1, 32>>>();   // keeps ncu capture slot on gemm_kernel
    convert_x_kernel<<<(DIM_M * DIM_K) / 8192, 256>>>(x);
    convert_xb_kernel<<<(DIM_M * KMW4) / 256, 256>>>(x);
    convert_w_kernel<<<dim3(DIM_N / 32, DIM_K / 32), dim3(32, 8)>>>(W);
    gemm_kernel<<<dim3(DIM_N / BN, DIM_M / BM), 512, SMEM_TOTAL>>>(bias, out);
}